// round 13
// baseline (speedup 1.0000x reference)
#include <cuda_runtime.h>
#include <math.h>
#include <stdint.h>

#define N_NODES 100000
#define N_EDGES 1600000
#define D_FEAT  64
#define EPS     1e-7f
#define FULL    0xffffffffu

// Scratch
__device__ float g_inv[N_NODES];          // 1 / ||x_i||
__device__ int   g_col[N_EDGES];          // edge_col as int32
__device__ int   g_rowptr[N_NODES + 1];

// ---------------------------------------------------------------------------
// Packed f32x2 helpers (sm_100+).
// ---------------------------------------------------------------------------
__device__ __forceinline__ uint64_t ffma2(uint64_t a, uint64_t b, uint64_t c)
{
    uint64_t r;
    asm("fma.rn.f32x2 %0, %1, %2, %3;" : "=l"(r) : "l"(a), "l"(b), "l"(c));
    return r;
}
__device__ __forceinline__ uint64_t pk2(float lo, float hi)
{
    uint64_t r;
    asm("mov.b64 %0, {%1, %2};" : "=l"(r) : "f"(lo), "f"(hi));
    return r;
}
__device__ __forceinline__ void upk2(uint64_t v, float& lo, float& hi)
{
    asm("mov.b64 {%0, %1}, %2;" : "=f"(lo), "=f"(hi) : "l"(v));
}

// ---------------------------------------------------------------------------
__device__ __forceinline__ int detect_is64(const unsigned int* ec_raw)
{
    unsigned acc = 0;
    #pragma unroll
    for (int i = 1; i < 16; i += 2) acc |= ec_raw[i];
    return acc == 0u;
}

__device__ __forceinline__ int get_idx(const void* p, int e, int is64)
{
    if (is64) return (int)((const long long*)p)[e];
    return ((const int*)p)[e];
}

// ---------------------------------------------------------------------------
// Prep kernel: three jobs via block-range split.
// ---------------------------------------------------------------------------
#define B_NORM 6250     // N_NODES*16 / 256
#define B_COL  6250     // N_EDGES / 256
#define B_ROW  391      // ceil((N_NODES+1)/256)

__global__ void __launch_bounds__(256)
prep_kernel(const float4* __restrict__ x4,
            const void* __restrict__ er,
            const void* __restrict__ ec)
{
    int b = blockIdx.x;
    if (b < B_NORM) {
        int t    = b * 256 + threadIdx.x;
        int node = t >> 4;
        int sub  = t & 15;
        if (node >= N_NODES) return;
        float4 a = x4[node * 16 + sub];
        float s = a.x * a.x + a.y * a.y + a.z * a.z + a.w * a.w;
        #pragma unroll
        for (int o = 8; o; o >>= 1) s += __shfl_xor_sync(FULL, s, o);
        if (sub == 0) g_inv[node] = rsqrtf(s);
    } else if (b < B_NORM + B_COL) {
        int e = (b - B_NORM) * 256 + threadIdx.x;
        if (e >= N_EDGES) return;
        int is64 = detect_is64((const unsigned int*)ec);
        g_col[e] = get_idx(ec, e, is64);
    } else {
        int i = (b - B_NORM - B_COL) * 256 + threadIdx.x;
        if (i > N_NODES) return;
        int is64 = detect_is64((const unsigned int*)ec);
        int lo = 0, hi = N_EDGES;
        while (lo < hi) {
            int mid = (lo + hi) >> 1;
            if (get_idx(er, mid, is64) < i) lo = mid + 1; else hi = mid;
        }
        g_rowptr[i] = lo;
    }
}

// ---------------------------------------------------------------------------
// Fused sim + softmax + SPMM. ONE WARP PER ROW, 4 edge-groups x 8 lanes,
// FFMA2 packed math, explicit register double-buffer: iteration it+1's
// gathers are issued before iteration it's dot/exp/acc chain.
// w = exp(beta*(cos-1)): shift-invariant softmax, arg<=0, no running max.
// ---------------------------------------------------------------------------
__global__ void __launch_bounds__(256, 5)
fused_row_kernel(const ulonglong2* __restrict__ x2,
                 const float* __restrict__ beta,
                 float4* __restrict__ out4)
{
    int warp = (blockIdx.x * blockDim.x + threadIdx.x) >> 5;
    if (warp >= N_NODES) return;
    int lane = threadIdx.x & 31;
    int g = lane >> 3;                    // edge slot within iteration
    int f = lane & 7;                     // feature slice

    int row = warp;
    int s = g_rowptr[row];
    int n = g_rowptr[row + 1] - s;

    ulonglong2 xr0 = x2[row * 16 + f];
    ulonglong2 xr1 = x2[row * 16 + 8 + f];
    float  bv = beta[0];
    float  bs = bv * g_inv[row];          // beta / ||x_r||

    uint64_t acc00 = 0, acc01 = 0, acc10 = 0, acc11 = 0;
    float    wsum  = 0.f;

    const int* __restrict__ col = g_col;

    for (int base = 0; base < n; base += 32) {
        int rem = n - base;
        int cnt = rem < 32 ? rem : 32;

        // cooperative prefetch of up to 32 indices + inverse norms
        int   myc   = (lane < cnt) ? col[s + base + lane] : row;
        float myinv = g_inv[myc];
        int iters = (cnt + 3) >> 2;

        // pipeline prologue: load slot 0's data
        int   c  = __shfl_sync(FULL, myc, g);
        float ic = __shfl_sync(FULL, myinv, g);
        ulonglong2 b0 = x2[c * 16 + f];
        ulonglong2 b1 = x2[c * 16 + 8 + f];

        for (int it = 0; it < iters; ++it) {
            // issue NEXT iteration's broadcasts + gathers first
            int  srcn = ((it + 1) << 2) + g;
            int  srcc = srcn < 32 ? srcn : g;          // keep shfl src legal
            int   cn  = __shfl_sync(FULL, myc,  srcc);
            float icn = __shfl_sync(FULL, myinv, srcc);
            ulonglong2 nb0 = x2[cn * 16 + f];
            ulonglong2 nb1 = x2[cn * 16 + 8 + f];

            // compute CURRENT iteration
            bool valid = ((it << 2) + g) < cnt;

            uint64_t d2 = ffma2(xr0.x, b0.x, 0ull);
            d2 = ffma2(xr0.y, b0.y, d2);
            d2 = ffma2(xr1.x, b1.x, d2);
            d2 = ffma2(xr1.y, b1.y, d2);
            float dlo, dhi; upk2(d2, dlo, dhi);
            float d = dlo + dhi;
            d += __shfl_xor_sync(FULL, d, 1);
            d += __shfl_xor_sync(FULL, d, 2);
            d += __shfl_xor_sync(FULL, d, 4);

            float w = __expf(fmaf(bs * ic, d, -bv));   // exp(beta*(cos-1))
            w = valid ? w : 0.f;
            uint64_t w2 = pk2(w, w);

            wsum += w;
            acc00 = ffma2(w2, b0.x, acc00);
            acc01 = ffma2(w2, b0.y, acc01);
            acc10 = ffma2(w2, b1.x, acc10);
            acc11 = ffma2(w2, b1.y, acc11);

            // rotate buffers
            b0 = nb0; b1 = nb1; ic = icn;
        }
    }

    // unpack accumulators, reduce the 4 edge-groups
    float a0, a1, a2, a3, a4, a5, a6, a7;
    upk2(acc00, a0, a1);
    upk2(acc01, a2, a3);
    upk2(acc10, a4, a5);
    upk2(acc11, a6, a7);

    #pragma unroll
    for (int o = 8; o <= 16; o <<= 1) {
        a0 += __shfl_xor_sync(FULL, a0, o);
        a1 += __shfl_xor_sync(FULL, a1, o);
        a2 += __shfl_xor_sync(FULL, a2, o);
        a3 += __shfl_xor_sync(FULL, a3, o);
        a4 += __shfl_xor_sync(FULL, a4, o);
        a5 += __shfl_xor_sync(FULL, a5, o);
        a6 += __shfl_xor_sync(FULL, a6, o);
        a7 += __shfl_xor_sync(FULL, a7, o);
        wsum += __shfl_xor_sync(FULL, wsum, o);
    }

    if (g == 0) {
        float invw = (n > 0) ? (1.f / wsum) : 0.f;
        out4[row * 16 + f]     = make_float4(a0 * invw, a1 * invw,
                                             a2 * invw, a3 * invw);
        out4[row * 16 + 8 + f] = make_float4(a4 * invw, a5 * invw,
                                             a6 * invw, a7 * invw);
    }
}

// ---------------------------------------------------------------------------
extern "C" void kernel_launch(void* const* d_in, const int* in_sizes, int n_in,
                              void* d_out, int out_size)
{
    const float4* x    = 0;
    const float*  beta = 0;
    const void*   er   = 0;
    const void*   ec   = 0;
    for (int i = 0; i < n_in; ++i) {
        long long sz = in_sizes[i];
        if (sz == (long long)N_NODES * D_FEAT) x = (const float4*)d_in[i];
        else if (sz == 1)                      beta = (const float*)d_in[i];
        else if (sz == N_EDGES) {
            if (!er) er = d_in[i]; else ec = d_in[i];
        }
    }
    float4* out = (float4*)d_out;

    prep_kernel<<<B_NORM + B_COL + B_ROW, 256>>>(x, er, ec);

    {   // one warp per row
        long long total = (long long)N_NODES * 32;
        int blocks = (int)((total + 255) / 256);
        fused_row_kernel<<<blocks, 256>>>((const ulonglong2*)x, beta, out);
    }
}

// round 14
// speedup vs baseline: 1.4586x; 1.4586x over previous
#include <cuda_runtime.h>
#include <math.h>
#include <stdint.h>

#define N_NODES 100000
#define N_EDGES 1600000
#define D_FEAT  64
#define EPS     1e-7f
#define FULL    0xffffffffu

// Scratch
__device__ float g_inv[N_NODES];          // 1 / ||x_i||
__device__ int   g_col[N_EDGES];          // edge_col as int32
__device__ int   g_rowptr[N_NODES + 1];

// ---------------------------------------------------------------------------
__device__ __forceinline__ void cp_async16(void* smem_dst, const void* gsrc)
{
    uint32_t d = (uint32_t)__cvta_generic_to_shared(smem_dst);
    asm volatile("cp.async.cg.shared.global [%0], [%1], 16;" :: "r"(d), "l"(gsrc));
}
#define CP_COMMIT() asm volatile("cp.async.commit_group;" ::: "memory")
#define CP_WAIT(n)  asm volatile("cp.async.wait_group %0;" :: "n"(n) : "memory")

// ---------------------------------------------------------------------------
__device__ __forceinline__ int detect_is64(const unsigned int* ec_raw)
{
    unsigned acc = 0;
    #pragma unroll
    for (int i = 1; i < 16; i += 2) acc |= ec_raw[i];
    return acc == 0u;
}

__device__ __forceinline__ int get_idx(const void* p, int e, int is64)
{
    if (is64) return (int)((const long long*)p)[e];
    return ((const int*)p)[e];
}

// ---------------------------------------------------------------------------
// Prep kernel: three jobs via block-range split (unchanged from R6).
// ---------------------------------------------------------------------------
#define B_NORM 6250     // N_NODES*16 / 256
#define B_COL  6250     // N_EDGES / 256
#define B_ROW  391      // ceil((N_NODES+1)/256)

__global__ void __launch_bounds__(256)
prep_kernel(const float4* __restrict__ x4,
            const void* __restrict__ er,
            const void* __restrict__ ec)
{
    int b = blockIdx.x;
    if (b < B_NORM) {
        int t    = b * 256 + threadIdx.x;
        int node = t >> 4;
        int sub  = t & 15;
        if (node >= N_NODES) return;
        float4 a = x4[node * 16 + sub];
        float s = a.x * a.x + a.y * a.y + a.z * a.z + a.w * a.w;
        #pragma unroll
        for (int o = 8; o; o >>= 1) s += __shfl_xor_sync(FULL, s, o);
        if (sub == 0) g_inv[node] = rsqrtf(s);
    } else if (b < B_NORM + B_COL) {
        int e = (b - B_NORM) * 256 + threadIdx.x;
        if (e >= N_EDGES) return;
        int is64 = detect_is64((const unsigned int*)ec);
        g_col[e] = get_idx(ec, e, is64);
    } else {
        int i = (b - B_NORM - B_COL) * 256 + threadIdx.x;
        if (i > N_NODES) return;
        int is64 = detect_is64((const unsigned int*)ec);
        int lo = 0, hi = N_EDGES;
        while (lo < hi) {
            int mid = (lo + hi) >> 1;
            if (get_idx(er, mid, is64) < i) lo = mid + 1; else hi = mid;
        }
        g_rowptr[i] = lo;
    }
}

// ---------------------------------------------------------------------------
// Fused sim + softmax + SPMM. ONE WARP PER ROW. Gathered neighbor rows are
// staged into shared memory by cp.async (double-buffered 8-edge groups), so
// gather latency never sits on the register dependency chain. Compute reads
// smem (LDS, 29 cyc), does the FMA dot, 3-shfl reduce, exp, accumulate —
// exactly the R6 economy. w = exp(beta*(cos-1)), shift-invariant, arg <= 0.
// ---------------------------------------------------------------------------
#define GRP 8                             // edges per pipeline stage
#define STAGE_BYTES (GRP * 256)           // 8 edges x 256 B

__global__ void __launch_bounds__(256)
fused_row_kernel(const float4* __restrict__ x4,
                 const char*   __restrict__ xraw,
                 const float*  __restrict__ beta,
                 float4* __restrict__ out4)
{
    __shared__ alignas(16) char sbuf[8][2][STAGE_BYTES];   // 32 KB

    int warp = (blockIdx.x * blockDim.x + threadIdx.x) >> 5;
    if (warp >= N_NODES) return;
    int lane = threadIdx.x & 31;
    int wib  = threadIdx.x >> 5;
    int g = lane >> 3;                    // edge slot (0..3) in compute
    int f = lane & 7;                     // feature slice in compute
    int le = lane >> 4;                   // edge parity (0..1) in copy
    int lb = lane & 15;                   // 16B slice (0..15) in copy

    int row = warp;
    int s = g_rowptr[row];
    int n = g_rowptr[row + 1] - s;

    if (n == 0) {
        if (g == 0) {
            out4[row * 16 + f]     = make_float4(0.f, 0.f, 0.f, 0.f);
            out4[row * 16 + 8 + f] = make_float4(0.f, 0.f, 0.f, 0.f);
        }
        return;
    }

    float4 xr0 = x4[row * 16 + f];
    float4 xr1 = x4[row * 16 + 8 + f];
    float  bv  = beta[0];
    float  bs  = bv * g_inv[row];         // beta / ||x_r||

    float4 acc0 = make_float4(0.f, 0.f, 0.f, 0.f);
    float4 acc1 = make_float4(0.f, 0.f, 0.f, 0.f);
    float  wsum = 0.f;

    const int* __restrict__ col = g_col;

    for (int base = 0; base < n; base += 32) {
        int rem = n - base;
        int cnt = rem < 32 ? rem : 32;
        int ngroups = (cnt + GRP - 1) / GRP;

        // prefetch up to 32 indices + inverse norms for this chunk
        int   myc   = (lane < cnt) ? col[s + base + lane] : row;
        float myinv = g_inv[myc];

        // issue group 0
        {
            #pragma unroll
            for (int i = 0; i < 4; ++i) {
                int eslot = le + 2 * i;                  // 0..7
                int c = __shfl_sync(FULL, myc, eslot);
                cp_async16(&sbuf[wib][0][eslot * 256 + lb * 16],
                           xraw + (long long)c * 256 + lb * 16);
            }
            CP_COMMIT();
        }

        for (int gi = 0; gi < ngroups; ++gi) {
            if (gi + 1 < ngroups) {
                // issue next group into the other stage
                #pragma unroll
                for (int i = 0; i < 4; ++i) {
                    int eslot = le + 2 * i;
                    int e = (gi + 1) * GRP + eslot;      // <= 31
                    int c = __shfl_sync(FULL, myc, e);
                    cp_async16(&sbuf[wib][(gi + 1) & 1][eslot * 256 + lb * 16],
                               xraw + (long long)c * 256 + lb * 16);
                }
                CP_COMMIT();
                CP_WAIT(1);                              // group gi complete
            } else {
                CP_WAIT(0);
            }
            __syncwarp();

            const char* buf = sbuf[wib][gi & 1];

            // compute 8 edges: 2 sub-iterations of 4 edge-groups
            #pragma unroll
            for (int sub = 0; sub < 2; ++sub) {
                int  eslot = sub * 4 + g;                // 0..7
                int  e     = gi * GRP + eslot;
                bool valid = e < cnt;
                float invnc = __shfl_sync(FULL, myinv, e & 31);

                float4 b0 = *(const float4*)(buf + eslot * 256 + f * 16);
                float4 b1 = *(const float4*)(buf + eslot * 256 + 128 + f * 16);

                float d = b0.x * xr0.x + b0.y * xr0.y + b0.z * xr0.z + b0.w * xr0.w
                        + b1.x * xr1.x + b1.y * xr1.y + b1.z * xr1.z + b1.w * xr1.w;
                d += __shfl_xor_sync(FULL, d, 1);
                d += __shfl_xor_sync(FULL, d, 2);
                d += __shfl_xor_sync(FULL, d, 4);

                float w = __expf(fmaf(bs * invnc, d, -bv));
                w = valid ? w : 0.f;

                wsum  += w;
                acc0.x = fmaf(w, b0.x, acc0.x);
                acc0.y = fmaf(w, b0.y, acc0.y);
                acc0.z = fmaf(w, b0.z, acc0.z);
                acc0.w = fmaf(w, b0.w, acc0.w);
                acc1.x = fmaf(w, b1.x, acc1.x);
                acc1.y = fmaf(w, b1.y, acc1.y);
                acc1.z = fmaf(w, b1.z, acc1.z);
                acc1.w = fmaf(w, b1.w, acc1.w);
            }
            __syncwarp();    // all lanes done reading before stage reuse
        }
    }

    // reduce the 4 edge-groups (butterfly -> all lanes hold totals)
    #pragma unroll
    for (int o = 8; o <= 16; o <<= 1) {
        acc0.x += __shfl_xor_sync(FULL, acc0.x, o);
        acc0.y += __shfl_xor_sync(FULL, acc0.y, o);
        acc0.z += __shfl_xor_sync(FULL, acc0.z, o);
        acc0.w += __shfl_xor_sync(FULL, acc0.w, o);
        acc1.x += __shfl_xor_sync(FULL, acc1.x, o);
        acc1.y += __shfl_xor_sync(FULL, acc1.y, o);
        acc1.z += __shfl_xor_sync(FULL, acc1.z, o);
        acc1.w += __shfl_xor_sync(FULL, acc1.w, o);
        wsum   += __shfl_xor_sync(FULL, wsum,   o);
    }

    if (g == 0) {
        float invw = 1.f / wsum;
        out4[row * 16 + f]     = make_float4(acc0.x * invw, acc0.y * invw,
                                             acc0.z * invw, acc0.w * invw);
        out4[row * 16 + 8 + f] = make_float4(acc1.x * invw, acc1.y * invw,
                                             acc1.z * invw, acc1.w * invw);
    }
}

// ---------------------------------------------------------------------------
extern "C" void kernel_launch(void* const* d_in, const int* in_sizes, int n_in,
                              void* d_out, int out_size)
{
    const float4* x    = 0;
    const float*  beta = 0;
    const void*   er   = 0;
    const void*   ec   = 0;
    for (int i = 0; i < n_in; ++i) {
        long long sz = in_sizes[i];
        if (sz == (long long)N_NODES * D_FEAT) x = (const float4*)d_in[i];
        else if (sz == 1)                      beta = (const float*)d_in[i];
        else if (sz == N_EDGES) {
            if (!er) er = d_in[i]; else ec = d_in[i];
        }
    }
    float4* out = (float4*)d_out;

    prep_kernel<<<B_NORM + B_COL + B_ROW, 256>>>(x, er, ec);

    {   // one warp per row
        long long total = (long long)N_NODES * 32;
        int blocks = (int)((total + 255) / 256);
        fused_row_kernel<<<blocks, 256>>>(x, (const char*)x, beta, out);
    }
}